// round 14
// baseline (speedup 1.0000x reference)
#include <cuda_runtime.h>
#include <cuda_fp16.h>
#include <math.h>
#include <stdint.h>

#define TT 512
#define NN 1024
#define DD 256
#define M_ROWS (TT * NN)

__device__ float g_e[M_ROWS];
__device__ __align__(16) __half g_Whi[DD * DD];
// attend scan carry (online-softmax state across chunk kernels)
__device__ float g_m[NN];
__device__ float g_s[NN];
__device__ __align__(16) float g_num[NN * DD];

// ---------------------------------------------------------------------------
// SMEM (per CTA, 57344 B -> 3 CTAs/SM = 168 KB; attend blocks add ~3.6 KB).
// ---------------------------------------------------------------------------
#define SA_OFF  0
#define SA_ROW  528
#define SB_OFF  33792
#define SB_SZ   10240
#define SBIAS   54272
#define SSW     55296
#define SRED    56320
#define SMTOT   57344

// ---------------------------------------------------------------------------
// PTX helpers (baseline ISA only -- toolchain targets sm_103, no tcgen05)
// ---------------------------------------------------------------------------
__device__ __forceinline__ uint32_t smem_u32(const void* p) {
    uint32_t a;
    asm("{ .reg .u64 t; cvta.to.shared.u64 t, %1; cvt.u32.u64 %0, t; }"
        : "=r"(a) : "l"(p));
    return a;
}
__device__ __forceinline__ void cp_async16(uint32_t dst, const void* src) {
    asm volatile("cp.async.cg.shared.global [%0], [%1], 16;"
                 :: "r"(dst), "l"(src) : "memory");
}
#define CP_COMMIT() asm volatile("cp.async.commit_group;" ::: "memory")
#define CP_WAIT(n)  asm volatile("cp.async.wait_group %0;" :: "n"(n) : "memory")

__device__ __forceinline__ void ldsm4(uint32_t* r, uint32_t addr) {
    asm volatile("ldmatrix.sync.aligned.m8n8.x4.shared.b16 {%0,%1,%2,%3}, [%4];"
                 : "=r"(r[0]), "=r"(r[1]), "=r"(r[2]), "=r"(r[3]) : "r"(addr));
}
__device__ __forceinline__ void mma16816(float* c, const uint32_t* a,
                                         uint32_t b0, uint32_t b1) {
    asm volatile(
        "mma.sync.aligned.m16n8k16.row.col.f32.f16.f16.f32 "
        "{%0,%1,%2,%3}, {%4,%5,%6,%7}, {%8,%9}, {%0,%1,%2,%3};"
        : "+f"(c[0]), "+f"(c[1]), "+f"(c[2]), "+f"(c[3])
        : "r"(a[0]), "r"(a[1]), "r"(a[2]), "r"(a[3]), "r"(b0), "r"(b1));
}

// fp32 x8 -> fp16 x8
__device__ __forceinline__ uint4 cvt8hi(const float4& u, const float4& v) {
    __half2 h0 = __floats2half2_rn(u.x, u.y);
    __half2 h1 = __floats2half2_rn(u.z, u.w);
    __half2 h2 = __floats2half2_rn(v.x, v.y);
    __half2 h3 = __floats2half2_rn(v.z, v.w);
    uint4 hi;
    hi.x = *(uint32_t*)&h0; hi.y = *(uint32_t*)&h1;
    hi.z = *(uint32_t*)&h2; hi.w = *(uint32_t*)&h3;
    return hi;
}

// tanh via MUFU (EX2 + RCP), rel err ~1e-6
__device__ __forceinline__ float tanh_mufu(float z) {
    float u = __expf(2.0f * z);
    return 1.0f - __fdividef(2.0f, u + 1.0f);
}

// ---------------------------------------------------------------------------
__global__ void w_prep(const float* __restrict__ W) {
    int i = blockIdx.x * blockDim.x + threadIdx.x;
    const float4* p = reinterpret_cast<const float4*>(W) + i * 2;
    reinterpret_cast<uint4*>(g_Whi)[i] = cvt8hi(p[0], p[1]);
}

// ---------------------------------------------------------------------------
// Kernel A: fp16 HMMA GEMM, BM=64 x BN=256 in two 128-col passes.
// 256 threads, 3 CTAs/SM. IDENTICAL to R12/R13 (regs=80 defines the
// leftover register pool the attend blocks live in -- do not perturb).
// ---------------------------------------------------------------------------
__global__ __launch_bounds__(256, 3)
void gemm_score_hmma(const float* __restrict__ H,
                     const float* __restrict__ bias,
                     const float* __restrict__ swt,
                     int blk0)
{
    extern __shared__ char smem[];
    const uint32_t sb = smem_u32(smem);
    const int tid  = threadIdx.x;
    const int lane = tid & 31;
    const int warp = tid >> 5;          // 0..7
    const int wr   = warp & 1;          // row group 32*wr
    const int wc   = warp >> 1;         // col group 32*wc (within pass)
    const int row0 = (blockIdx.x + blk0) * 64;

    ((float*)(smem + SBIAS))[tid] = bias[tid];
    ((float*)(smem + SSW))[tid]   = swt[tid];

    const int lrow = lane & 15;
    const int lkh  = lane >> 4;
    const uint32_t aAddr = sb + SA_OFF +
                           (uint32_t)((wr * 32 + lrow) * SA_ROW + lkh * 16);
    const uint32_t bAddr = sb + SB_OFF +
                           (uint32_t)((wc * 32 + lrow) * 80 + lkh * 16);

    const float* sbias = (const float*)(smem + SBIAS);
    const float* ssw   = (const float*)(smem + SSW);

    float partAcc[2][2] = {{0.0f, 0.0f}, {0.0f, 0.0f}};

    #pragma unroll 1
    for (int pass = 0; pass < 2; pass++) {
        const __half* Bsrc = g_Whi + (size_t)pass * 128 * DD;

        auto cpB = [&](int c, int buf) {
            #pragma unroll
            for (int p = 0; p < 2; p++) {
                int idx = tid + p * 256;
                int r   = idx >> 2;
                int ch  = idx & 3;
                cp_async16(sb + SB_OFF + buf * SB_SZ + r * 80 + ch * 16,
                           Bsrc + (size_t)r * DD + c * 32 + ch * 8);
            }
            CP_COMMIT();
        };

        cpB(0, 0);
        if (pass == 0) {
            #pragma unroll
            for (int i = 0; i < 8; i++) {
                int slot = tid + i * 256;
                int r    = slot >> 5;
                int kseg = slot & 31;
                const float* src = H + (size_t)(row0 + r) * DD + kseg * 8;
                float4 u = *reinterpret_cast<const float4*>(src);
                float4 v = *reinterpret_cast<const float4*>(src + 4);
                *reinterpret_cast<uint4*>(smem + SA_OFF + r * SA_ROW +
                                          kseg * 16) = cvt8hi(u, v);
            }
        }
        CP_WAIT(0);
        __syncthreads();

        float acc[2][4][4];
        #pragma unroll
        for (int m = 0; m < 2; m++)
            #pragma unroll
            for (int j = 0; j < 4; j++)
                #pragma unroll
                for (int e = 0; e < 4; e++) acc[m][j][e] = 0.0f;

        #pragma unroll
        for (int c = 0; c < 8; c++) {
            const int buf = c & 1;
            if (c < 7) cpB(c + 1, buf ^ 1);

            const uint32_t aA = aAddr + (uint32_t)(c * 64);
            const uint32_t bB = bAddr + (uint32_t)(buf * SB_SZ);
            #pragma unroll
            for (int ks = 0; ks < 2; ks++) {
                uint32_t ah[2][4];
                ldsm4(ah[0], aA + ks * 32);
                ldsm4(ah[1], aA + 16 * SA_ROW + ks * 32);
                #pragma unroll
                for (int ntp = 0; ntp < 2; ntp++) {
                    uint32_t bf[4];
                    ldsm4(bf, bB + ntp * (16 * 80) + ks * 32);
                    #pragma unroll
                    for (int mt = 0; mt < 2; mt++) {
                        mma16816(acc[mt][ntp * 2 + 0], ah[mt], bf[0], bf[2]);
                        mma16816(acc[mt][ntp * 2 + 1], ah[mt], bf[1], bf[3]);
                    }
                }
            }
            if (c < 7) {
                CP_WAIT(0);
                __syncthreads();
            }
        }

        #pragma unroll
        for (int mt = 0; mt < 2; mt++) {
            #pragma unroll
            for (int h = 0; h < 2; h++) {
                float part = 0.0f;
                #pragma unroll
                for (int j = 0; j < 4; j++) {
                    const int col = pass * 128 + wc * 32 + j * 8 +
                                    (lane & 3) * 2;
                    float2 bb = *reinterpret_cast<const float2*>(&sbias[col]);
                    float2 ws = *reinterpret_cast<const float2*>(&ssw[col]);
                    part = fmaf(tanh_mufu(acc[mt][j][h * 2 + 0] + bb.x),
                                ws.x, part);
                    part = fmaf(tanh_mufu(acc[mt][j][h * 2 + 1] + bb.y),
                                ws.y, part);
                }
                partAcc[mt][h] += part;
            }
        }
    }

    float* sred = (float*)(smem + SRED);
    #pragma unroll
    for (int mt = 0; mt < 2; mt++) {
        #pragma unroll
        for (int h = 0; h < 2; h++) {
            float part = partAcc[mt][h];
            part += __shfl_xor_sync(0xffffffffu, part, 1);
            part += __shfl_xor_sync(0xffffffffu, part, 2);
            const int lrow_out = wr * 32 + mt * 16 + (lane >> 2) + h * 8;
            if ((lane & 3) == 0) sred[wc * 64 + lrow_out] = part;
        }
    }
    __syncthreads();
    if (tid < 64)
        g_e[row0 + tid] = (sred[tid] + sred[64 + tid]) +
                          (sred[128 + tid] + sred[192 + tid]);
}

// ---------------------------------------------------------------------------
// Kernel B: chunked causal softmax prefix average, EXTRA-SLIM: 32 threads,
// each owning 8 d's (two float4 chains). <=64 regs (launch_bounds 32,32)
// -> ~1.5-2K regs per block -> up to 3 blocks co-resident in the 4K-reg
// leftover beside 3 GEMM CTAs. Waves per chunk drop 7 -> ~2.3.
// ---------------------------------------------------------------------------
__global__ __launch_bounds__(32, 32)
void attend_chunk(const float* __restrict__ H, float* __restrict__ C,
                  int t0, int t1, int first)
{
    __shared__ float sal[96];   // alpha
    __shared__ float sp[96];    // p
    __shared__ float siv[96];   // 1/s

    const int n   = blockIdx.x;
    const int tid = threadIdx.x;
    const int len = t1 - t0;

    for (int i = tid; i < len; i += 32)
        sal[i] = g_e[(size_t)(t0 + i) * NN + n];
    __syncwarp();

    if (tid == 0) {
        float m = first ? -INFINITY : g_m[n];
        float s = first ? 0.0f      : g_s[n];
        for (int i = 0; i < len; i++) {
            float e  = sal[i];
            float mn = fmaxf(m, e);
            float a  = __expf(m - mn);
            float p  = __expf(e - mn);
            s = s * a + p;
            sal[i] = a;
            sp[i]  = p;
            siv[i] = __fdividef(1.0f, s);
            m = mn;
        }
        g_m[n] = m;
        g_s[n] = s;
    }
    __syncwarp();

    const size_t stride4 = (size_t)NN * (DD / 4);   // float4 per t
    const float4* hp = reinterpret_cast<const float4*>(H) +
                       (size_t)t0 * stride4 + (size_t)n * (DD / 4) + tid;
    float4* cp = reinterpret_cast<float4*>(C) +
                 (size_t)t0 * stride4 + (size_t)n * (DD / 4) + tid;
    float4* gn = reinterpret_cast<float4*>(g_num) + (size_t)n * (DD / 4) + tid;

    float4 n0, n1;
    if (first) {
        n0 = make_float4(0.f, 0.f, 0.f, 0.f);
        n1 = make_float4(0.f, 0.f, 0.f, 0.f);
    } else {
        n0 = gn[0];
        n1 = gn[32];
    }

    #pragma unroll 4
    for (int i = 0; i < len; i++) {
        float4 h0 = hp[(size_t)i * stride4];
        float4 h1 = hp[(size_t)i * stride4 + 32];
        float a = sal[i], p = sp[i], si = siv[i];
        n0.x = fmaf(n0.x, a, p * h0.x);
        n0.y = fmaf(n0.y, a, p * h0.y);
        n0.z = fmaf(n0.z, a, p * h0.z);
        n0.w = fmaf(n0.w, a, p * h0.w);
        n1.x = fmaf(n1.x, a, p * h1.x);
        n1.y = fmaf(n1.y, a, p * h1.y);
        n1.z = fmaf(n1.z, a, p * h1.z);
        n1.w = fmaf(n1.w, a, p * h1.w);
        float4 o0 = make_float4(n0.x * si, n0.y * si, n0.z * si, n0.w * si);
        float4 o1 = make_float4(n1.x * si, n1.y * si, n1.z * si, n1.w * si);
        __stcs(cp + (size_t)i * stride4, o0);
        __stcs(cp + (size_t)i * stride4 + 32, o1);
    }
    gn[0]  = n0;
    gn[32] = n1;
}

// ---------------------------------------------------------------------------
// Stream/event plumbing (global ctor; no device-memory APIs).
// ---------------------------------------------------------------------------
#define NCHUNK 8
namespace {
struct Plumbing {
    cudaStream_t s2;
    cudaEvent_t  evG[NCHUNK];
    cudaEvent_t  evJ;
    Plumbing() {
        int lo = 0, hi = 0;
        cudaDeviceGetStreamPriorityRange(&lo, &hi);
        cudaStreamCreateWithPriority(&s2, cudaStreamNonBlocking, hi);
        for (int i = 0; i < NCHUNK; i++)
            cudaEventCreateWithFlags(&evG[i], cudaEventDisableTiming);
        cudaEventCreateWithFlags(&evJ, cudaEventDisableTiming);
    }
};
Plumbing g_plumb;
}

// 3 CTAs/SM -> 444 blocks/wave; chunks of 1328 (~3 waves, /16-aligned).
static const int kBlk[NCHUNK + 1] =
    {0, 1328, 2656, 3984, 5312, 6640, 7968, 8096, 8192};

// ---------------------------------------------------------------------------
extern "C" void kernel_launch(void* const* d_in, const int* in_sizes, int n_in,
                              void* d_out, int out_size)
{
    const float* H  = (const float*)d_in[0];
    const float* W  = (const float*)d_in[1];
    const float* b  = (const float*)d_in[2];
    const float* sv = (const float*)d_in[3];
    float* C = (float*)d_out;

    cudaFuncSetAttribute(gemm_score_hmma,
                         cudaFuncAttributeMaxDynamicSharedMemorySize, SMTOT);

    w_prep<<<16, 512>>>(W);

    for (int c = 0; c < NCHUNK; c++) {
        gemm_score_hmma<<<kBlk[c + 1] - kBlk[c], 256, SMTOT>>>(H, b, sv, kBlk[c]);
        cudaEventRecord(g_plumb.evG[c], 0);
    }
    for (int c = 0; c < NCHUNK; c++) {
        cudaStreamWaitEvent(g_plumb.s2, g_plumb.evG[c], 0);
        attend_chunk<<<NN, 32, 0, g_plumb.s2>>>(H, C, kBlk[c] / 16,
                                                kBlk[c + 1] / 16, c == 0);
    }
    cudaEventRecord(g_plumb.evJ, g_plumb.s2);
    cudaStreamWaitEvent(0, g_plumb.evJ, 0);
}